// round 6
// baseline (speedup 1.0000x reference)
#include <cuda_runtime.h>
#include <cstddef>

#define BATCH 16
#define C0    1024
#define C1    512
#define LEN   2048
#define BC    256
#define RC    64
#define NB0   4
#define NB1   2
#define NK    (NB0 + NB1)
#define EPSV  1e-5f

#define TPB   (BC + C0 + C1)      // tasks per batch: 256 reduce + 1536 scale = 1792
#define NTASK (BATCH * TPB)
#define GRID  1184                // 148 SMs x 8 CTAs, all co-resident

// scratch + sync flags (allocation-free rule: __device__ globals)
__device__ float g_gap[BATCH * BC];
__device__ float g_atten[NK * BATCH * BC];
__device__ int   g_done[BATCH];
__device__ int   g_ready[BATCH];

// ---------------------------------------------------------------------------
__global__ void zero_flags_kernel() {
    if (threadIdx.x < BATCH) {
        g_done[threadIdx.x]  = 0;
        g_ready[threadIdx.x] = 0;
    }
}

// ---------------------------------------------------------------------------
// One persistent kernel. Task list per batch b:
//   ids [0, 256)    : reduce task (b, c)  -- 6 rows of 2048 f32
//   ids [256, 1792) : scale task row r    -- read row (L2-hot), write out
// The 256th reduce arriver computes atten for the batch and sets ready[b].
// Scale tasks spin on ready[b]. All CTAs are co-resident -> no deadlock.
// NOTE: all shared arrays accessed through float4 casts are __align__(16)
// (R5 trap: s_gap at offset 36 -> misaligned LDS.128).
// ---------------------------------------------------------------------------
__global__ __launch_bounds__(256, 8) void fused_kernel(
    const float* __restrict__ x0, const float* __restrict__ x1,
    const float* __restrict__ W_joint, const float* __restrict__ b_joint,
    const float* __restrict__ bn_gamma, const float* __restrict__ bn_beta,
    const float* __restrict__ bn_mean, const float* __restrict__ bn_var,
    const float* __restrict__ W_group, const float* __restrict__ b_group,
    float* __restrict__ out)
{
    const int t = threadIdx.x;

    __shared__ __align__(16) float s_gap[BC];
    __shared__ __align__(16) float s_h[RC];
    __shared__ __align__(16) float s_red[8];
    __shared__ int s_last;

    for (int task = blockIdx.x; task < NTASK; task += GRID) {
        const int b = task / TPB;
        const int r = task % TPB;

        if (r < BC) {
            // ---------------- reduce task: (b, c = r) ----------------
            const int c = r;
            float sum = 0.0f;

            #pragma unroll
            for (int nb = 0; nb < NB0; nb++) {
                const float4* p = (const float4*)(x0 + (size_t)(b * C0 + nb * BC + c) * LEN);
                float4 v0 = p[t];
                float4 v1 = p[t + 256];
                sum += v0.x + v0.y + v0.z + v0.w;
                sum += v1.x + v1.y + v1.z + v1.w;
            }
            #pragma unroll
            for (int nb = 0; nb < NB1; nb++) {
                const float4* p = (const float4*)(x1 + (size_t)(b * C1 + nb * BC + c) * LEN);
                float4 v0 = p[t];
                float4 v1 = p[t + 256];
                sum += v0.x + v0.y + v0.z + v0.w;
                sum += v1.x + v1.y + v1.z + v1.w;
            }

            #pragma unroll
            for (int o = 16; o; o >>= 1) sum += __shfl_down_sync(0xffffffffu, sum, o);
            if ((t & 31) == 0) s_red[t >> 5] = sum;
            __syncthreads();
            if (t == 0) {
                float s = s_red[0];
                #pragma unroll
                for (int w = 1; w < 8; w++) s += s_red[w];
                g_gap[b * BC + c] = s * (1.0f / (float)LEN);
                __threadfence();
                int v = atomicAdd(&g_done[b], 1);
                s_last = (v == BC - 1);
            }
            __syncthreads();

            if (s_last) {
                // -------- this CTA finishes batch b: compute attention --------
                __threadfence();
                s_gap[t] = __ldcg(&g_gap[b * BC + t]);
                __syncthreads();

                if (t < RC) {
                    float acc = b_joint[t];
                    const float4* w  = (const float4*)(W_joint + t * BC);
                    const float4* g4 = (const float4*)s_gap;
                    #pragma unroll 4
                    for (int c4 = 0; c4 < BC / 4; c4++) {
                        float4 wv = w[c4];
                        float4 gv = g4[c4];
                        acc += wv.x * gv.x + wv.y * gv.y + wv.z * gv.z + wv.w * gv.w;
                    }
                    acc = (acc - bn_mean[t]) * rsqrtf(bn_var[t] + EPSV) * bn_gamma[t] + bn_beta[t];
                    s_h[t] = fmaxf(acc, 0.0f);
                }
                __syncthreads();

                float lg[NK];
                #pragma unroll
                for (int k = 0; k < NK; k++) {
                    float acc = b_group[k * BC + t];
                    const float4* w = (const float4*)(W_group + (size_t)(k * BC + t) * RC);
                    #pragma unroll 4
                    for (int r4 = 0; r4 < RC / 4; r4++) {
                        float4 wv = w[r4];
                        acc += s_h[4 * r4 + 0] * wv.x + s_h[4 * r4 + 1] * wv.y
                             + s_h[4 * r4 + 2] * wv.z + s_h[4 * r4 + 3] * wv.w;
                    }
                    lg[k] = acc;
                }
                float m = lg[0];
                #pragma unroll
                for (int k = 1; k < NK; k++) m = fmaxf(m, lg[k]);
                float ssum = 0.0f;
                #pragma unroll
                for (int k = 0; k < NK; k++) { lg[k] = expf(lg[k] - m); ssum += lg[k]; }
                const float inv = 1.0f / ssum;
                #pragma unroll
                for (int k = 0; k < NK; k++)
                    g_atten[k * (BATCH * BC) + b * BC + t] = lg[k] * inv;

                __threadfence();
                __syncthreads();
                if (t == 0) atomicExch(&g_ready[b], 1);
            }
            __syncthreads();   // protect shared reuse next iteration
        } else {
            // ---------------- scale task: batch b, row rr ----------------
            const int rr = r - BC;   // 0..1535

            if (t == 0) {
                while (atomicAdd(&g_ready[b], 0) == 0) __nanosleep(128);
            }
            __syncthreads();
            __threadfence();

            const float4* src;
            float4* dst;
            float scale;

            if (rr < C0) {
                const int nb = rr >> 8;
                const int c  = rr & (BC - 1);
                scale = __ldcg(&g_atten[nb * (BATCH * BC) + b * BC + c]);
                const size_t row = (size_t)b * C0 + rr;
                src = (const float4*)(x0 + row * LEN);
                dst = (float4*)(out + row * LEN);
            } else {
                const int r1 = rr - C0;
                const int nb = r1 >> 8;
                const int c  = r1 & (BC - 1);
                scale = __ldcg(&g_atten[(NB0 + nb) * (BATCH * BC) + b * BC + c]);
                const size_t row = (size_t)b * C1 + r1;
                src = (const float4*)(x1 + row * LEN);
                dst = (float4*)(out + (size_t)(BATCH * C0) * LEN + row * LEN);
            }

            float4 v0 = src[t];
            float4 v1 = src[t + 256];
            v0.x *= scale; v0.y *= scale; v0.z *= scale; v0.w *= scale;
            v1.x *= scale; v1.y *= scale; v1.z *= scale; v1.w *= scale;
            __stcs(dst + t,       v0);
            __stcs(dst + t + 256, v1);
        }
    }
}

// ---------------------------------------------------------------------------
extern "C" void kernel_launch(void* const* d_in, const int* in_sizes, int n_in,
                              void* d_out, int out_size) {
    const float* x0       = (const float*)d_in[0];
    const float* x1       = (const float*)d_in[1];
    const float* W_joint  = (const float*)d_in[2];
    const float* b_joint  = (const float*)d_in[3];
    const float* bn_gamma = (const float*)d_in[4];
    const float* bn_beta  = (const float*)d_in[5];
    const float* bn_mean  = (const float*)d_in[6];
    const float* bn_var   = (const float*)d_in[7];
    const float* W_group  = (const float*)d_in[8];
    const float* b_group  = (const float*)d_in[9];
    float* out = (float*)d_out;

    zero_flags_kernel<<<1, 32>>>();
    fused_kernel<<<GRID, 256>>>(x0, x1, W_joint, b_joint, bn_gamma, bn_beta,
                                bn_mean, bn_var, W_group, b_group, out);
}

// round 7
// speedup vs baseline: 3.6476x; 3.6476x over previous
#include <cuda_runtime.h>
#include <cstddef>

#define BATCH 16
#define C0    1024
#define C1    512
#define LEN   2048
#define BC    256
#define RC    64
#define NB0   4
#define NB1   2
#define NK    (NB0 + NB1)
#define EPSV  1e-5f

#define NRED     (BATCH * BC)          // 4096 reduce tasks (batch-major)
#define SCALE_PB (C0 + C1)             // 1536 scale tasks per batch
#define NSCALE   (BATCH * SCALE_PB)    // 24576 scale tasks (batch-major)
#define GRID     1184                  // 148 SMs x 8 CTAs, co-resident

// scratch + scheduler state (allocation-free rule: __device__ globals)
__device__ float g_gap[BATCH * BC];
__device__ float g_atten[NK * BATCH * BC];
__device__ int   g_done[BATCH];
__device__ int   g_ready[BATCH];
__device__ int   g_red_ticket;
__device__ int   g_scale_ticket;

// ---------------------------------------------------------------------------
__global__ void zero_flags_kernel() {
    if (threadIdx.x < BATCH) {
        g_done[threadIdx.x]  = 0;
        g_ready[threadIdx.x] = 0;
    }
    if (threadIdx.x == 0) {
        g_red_ticket   = 0;
        g_scale_ticket = 0;
    }
}

// ---------------------------------------------------------------------------
// Persistent kernel with dynamic work stealing.
//   reduce task id r in [0, NRED):   b = r/BC, c = r%BC  (6 rows -> gap)
//   scale  task id s in [0, NSCALE): b = s/SCALE_PB, row = s%SCALE_PB
// CTA picks scale work when its head batch is ready, else reduce work.
// ---------------------------------------------------------------------------
__global__ __launch_bounds__(256, 8) void fused_kernel(
    const float* __restrict__ x0, const float* __restrict__ x1,
    const float* __restrict__ W_joint, const float* __restrict__ b_joint,
    const float* __restrict__ bn_gamma, const float* __restrict__ bn_beta,
    const float* __restrict__ bn_mean, const float* __restrict__ bn_var,
    const float* __restrict__ W_group, const float* __restrict__ b_group,
    float* __restrict__ out)
{
    const int t = threadIdx.x;

    __shared__ __align__(16) float s_gap[BC];
    __shared__ __align__(16) float s_h[RC];
    __shared__ __align__(16) float s_red[8];
    __shared__ int s_task;
    __shared__ int s_last;

    for (;;) {
        __syncthreads();   // protect s_task / shared reuse from previous iter
        if (t == 0) {
            int task = -1;                       // -1 retry, -2 exit
            const int sh = atomicAdd(&g_scale_ticket, 0);   // peek
            if (sh < NSCALE && atomicAdd(&g_ready[sh / SCALE_PB], 0) != 0) {
                const int s = atomicAdd(&g_scale_ticket, 1);
                if (s < NSCALE) task = NRED + s;
                else            task = -2;       // everything dispatched
            } else {
                const int r = atomicAdd(&g_red_ticket, 1);
                if (r < NRED) task = r;
                else if (sh >= NSCALE) task = -2;
                else { __nanosleep(128); task = -1; }
            }
            s_task = task;
        }
        __syncthreads();
        const int task = s_task;

        if (task == -2) break;
        if (task == -1) continue;

        if (task < NRED) {
            // ---------------- reduce task ----------------
            const int b = task / BC;
            const int c = task % BC;
            float sum = 0.0f;

            #pragma unroll
            for (int nb = 0; nb < NB0; nb++) {
                const float4* p = (const float4*)(x0 + (size_t)(b * C0 + nb * BC + c) * LEN);
                float4 v0 = p[t];
                float4 v1 = p[t + 256];
                sum += v0.x + v0.y + v0.z + v0.w;
                sum += v1.x + v1.y + v1.z + v1.w;
            }
            #pragma unroll
            for (int nb = 0; nb < NB1; nb++) {
                const float4* p = (const float4*)(x1 + (size_t)(b * C1 + nb * BC + c) * LEN);
                float4 v0 = p[t];
                float4 v1 = p[t + 256];
                sum += v0.x + v0.y + v0.z + v0.w;
                sum += v1.x + v1.y + v1.z + v1.w;
            }

            #pragma unroll
            for (int o = 16; o; o >>= 1) sum += __shfl_down_sync(0xffffffffu, sum, o);
            if ((t & 31) == 0) s_red[t >> 5] = sum;
            __syncthreads();
            if (t == 0) {
                float s = s_red[0];
                #pragma unroll
                for (int w = 1; w < 8; w++) s += s_red[w];
                g_gap[b * BC + c] = s * (1.0f / (float)LEN);
                __threadfence();
                int v = atomicAdd(&g_done[b], 1);
                s_last = (v == BC - 1);
            }
            __syncthreads();

            if (s_last) {
                // ---- last reducer of batch b: compute attention ----
                __threadfence();
                s_gap[t] = __ldcg(&g_gap[b * BC + t]);
                __syncthreads();

                if (t < RC) {
                    float acc = b_joint[t];
                    const float4* w  = (const float4*)(W_joint + t * BC);
                    const float4* g4 = (const float4*)s_gap;
                    #pragma unroll 4
                    for (int c4 = 0; c4 < BC / 4; c4++) {
                        float4 wv = w[c4];
                        float4 gv = g4[c4];
                        acc += wv.x * gv.x + wv.y * gv.y + wv.z * gv.z + wv.w * gv.w;
                    }
                    acc = (acc - bn_mean[t]) * rsqrtf(bn_var[t] + EPSV) * bn_gamma[t] + bn_beta[t];
                    s_h[t] = fmaxf(acc, 0.0f);
                }
                __syncthreads();

                float lg[NK];
                #pragma unroll
                for (int k = 0; k < NK; k++) {
                    float acc = b_group[k * BC + t];
                    const float4* w = (const float4*)(W_group + (size_t)(k * BC + t) * RC);
                    #pragma unroll 4
                    for (int r4 = 0; r4 < RC / 4; r4++) {
                        float4 wv = w[r4];
                        acc += s_h[4 * r4 + 0] * wv.x + s_h[4 * r4 + 1] * wv.y
                             + s_h[4 * r4 + 2] * wv.z + s_h[4 * r4 + 3] * wv.w;
                    }
                    lg[k] = acc;
                }
                float m = lg[0];
                #pragma unroll
                for (int k = 1; k < NK; k++) m = fmaxf(m, lg[k]);
                float ssum = 0.0f;
                #pragma unroll
                for (int k = 0; k < NK; k++) { lg[k] = expf(lg[k] - m); ssum += lg[k]; }
                const float inv = 1.0f / ssum;
                #pragma unroll
                for (int k = 0; k < NK; k++)
                    g_atten[k * (BATCH * BC) + b * BC + t] = lg[k] * inv;

                __threadfence();
                __syncthreads();
                if (t == 0) atomicExch(&g_ready[b], 1);
            }
        } else {
            // ---------------- scale task ----------------
            const int s  = task - NRED;
            const int b  = s / SCALE_PB;
            const int rr = s % SCALE_PB;

            if (t == 0) {
                // grabbed ticket might be one batch past the ready frontier
                while (atomicAdd(&g_ready[b], 0) == 0) __nanosleep(64);
            }
            __syncthreads();
            __threadfence();

            const float4* src;
            float4* dst;
            float scale;

            if (rr < C0) {
                const int nb = rr >> 8;
                const int c  = rr & (BC - 1);
                scale = __ldcg(&g_atten[nb * (BATCH * BC) + b * BC + c]);
                const size_t row = (size_t)b * C0 + rr;
                src = (const float4*)(x0 + row * LEN);
                dst = (float4*)(out + row * LEN);
            } else {
                const int r1 = rr - C0;
                const int nb = r1 >> 8;
                const int c  = r1 & (BC - 1);
                scale = __ldcg(&g_atten[(NB0 + nb) * (BATCH * BC) + b * BC + c]);
                const size_t row = (size_t)b * C1 + r1;
                src = (const float4*)(x1 + row * LEN);
                dst = (float4*)(out + (size_t)(BATCH * C0) * LEN + row * LEN);
            }

            float4 v0 = src[t];
            float4 v1 = src[t + 256];
            v0.x *= scale; v0.y *= scale; v0.z *= scale; v0.w *= scale;
            v1.x *= scale; v1.y *= scale; v1.z *= scale; v1.w *= scale;
            __stcs(dst + t,       v0);
            __stcs(dst + t + 256, v1);
        }
    }
}

// ---------------------------------------------------------------------------
extern "C" void kernel_launch(void* const* d_in, const int* in_sizes, int n_in,
                              void* d_out, int out_size) {
    const float* x0       = (const float*)d_in[0];
    const float* x1       = (const float*)d_in[1];
    const float* W_joint  = (const float*)d_in[2];
    const float* b_joint  = (const float*)d_in[3];
    const float* bn_gamma = (const float*)d_in[4];
    const float* bn_beta  = (const float*)d_in[5];
    const float* bn_mean  = (const float*)d_in[6];
    const float* bn_var   = (const float*)d_in[7];
    const float* W_group  = (const float*)d_in[8];
    const float* b_group  = (const float*)d_in[9];
    float* out = (float*)d_out;

    zero_flags_kernel<<<1, 32>>>();
    fused_kernel<<<GRID, 256>>>(x0, x1, W_joint, b_joint, bn_gamma, bn_beta,
                                bn_mean, bn_var, W_group, b_group, out);
}

// round 8
// speedup vs baseline: 3.8945x; 1.0677x over previous
#include <cuda_runtime.h>
#include <cstddef>

#define BATCH 16
#define C0    1024
#define C1    512
#define LEN   2048
#define BC    256
#define RC    64
#define NB0   4
#define NB1   2
#define NK    (NB0 + NB1)
#define EPSV  1e-5f

#define NRED      (BATCH * BC)            // 4096 reduce tickets (batch-major)
#define SCALE_PB  (C0 + C1)               // 1536 rows per batch
#define CH_ROWS   4                       // rows per scale ticket
#define CHUNKS_PB (SCALE_PB / CH_ROWS)    // 384
#define NSCHUNK   (BATCH * CHUNKS_PB)     // 6144 scale tickets (batch-major)
#define GRID      1184                    // 148 SMs x 8 CTAs, co-resident

// scratch + scheduler state (allocation-free rule: __device__ globals)
__device__ float g_gap[BATCH * BC];
__device__ float g_atten[NK * BATCH * BC];
__device__ int   g_done[BATCH];
__device__ int   g_ready[BATCH];
__device__ int   g_red_ticket;
__device__ int   g_scale_ticket;

// ---------------------------------------------------------------------------
__global__ void zero_flags_kernel() {
    if (threadIdx.x < BATCH) {
        g_done[threadIdx.x]  = 0;
        g_ready[threadIdx.x] = 0;
    }
    if (threadIdx.x == 0) {
        g_red_ticket   = 0;
        g_scale_ticket = 0;
    }
}

// ---------------------------------------------------------------------------
// Reduce task r: b = r/BC, c = r%BC. Whole CTA reduces 6 rows; last finisher
// of a batch computes attention in-block and publishes ready[b].
// ---------------------------------------------------------------------------
__device__ __forceinline__ void do_reduce_task(
    int task, int t,
    const float* __restrict__ x0, const float* __restrict__ x1,
    const float* __restrict__ W_joint, const float* __restrict__ b_joint,
    const float* __restrict__ bn_gamma, const float* __restrict__ bn_beta,
    const float* __restrict__ bn_mean, const float* __restrict__ bn_var,
    const float* __restrict__ W_group, const float* __restrict__ b_group,
    float* s_gap, float* s_h, float* s_red, int* p_last)
{
    const int b = task / BC;
    const int c = task % BC;
    float sum = 0.0f;

    #pragma unroll
    for (int nb = 0; nb < NB0; nb++) {
        const float4* p = (const float4*)(x0 + (size_t)(b * C0 + nb * BC + c) * LEN);
        float4 v0 = p[t];
        float4 v1 = p[t + 256];
        sum += v0.x + v0.y + v0.z + v0.w;
        sum += v1.x + v1.y + v1.z + v1.w;
    }
    #pragma unroll
    for (int nb = 0; nb < NB1; nb++) {
        const float4* p = (const float4*)(x1 + (size_t)(b * C1 + nb * BC + c) * LEN);
        float4 v0 = p[t];
        float4 v1 = p[t + 256];
        sum += v0.x + v0.y + v0.z + v0.w;
        sum += v1.x + v1.y + v1.z + v1.w;
    }

    #pragma unroll
    for (int o = 16; o; o >>= 1) sum += __shfl_down_sync(0xffffffffu, sum, o);
    if ((t & 31) == 0) s_red[t >> 5] = sum;
    __syncthreads();
    if (t == 0) {
        float s = s_red[0];
        #pragma unroll
        for (int w = 1; w < 8; w++) s += s_red[w];
        g_gap[b * BC + c] = s * (1.0f / (float)LEN);
        __threadfence();
        int v = atomicAdd(&g_done[b], 1);
        *p_last = (v == BC - 1);
    }
    __syncthreads();

    if (*p_last) {
        __threadfence();
        s_gap[t] = __ldcg(&g_gap[b * BC + t]);
        __syncthreads();

        if (t < RC) {
            float acc = b_joint[t];
            const float4* w  = (const float4*)(W_joint + t * BC);
            const float4* g4 = (const float4*)s_gap;
            #pragma unroll 4
            for (int c4 = 0; c4 < BC / 4; c4++) {
                float4 wv = w[c4];
                float4 gv = g4[c4];
                acc += wv.x * gv.x + wv.y * gv.y + wv.z * gv.z + wv.w * gv.w;
            }
            acc = (acc - bn_mean[t]) * rsqrtf(bn_var[t] + EPSV) * bn_gamma[t] + bn_beta[t];
            s_h[t] = fmaxf(acc, 0.0f);
        }
        __syncthreads();

        float lg[NK];
        #pragma unroll
        for (int k = 0; k < NK; k++) {
            float acc = b_group[k * BC + t];
            const float4* w = (const float4*)(W_group + (size_t)(k * BC + t) * RC);
            #pragma unroll 4
            for (int r4 = 0; r4 < RC / 4; r4++) {
                float4 wv = w[r4];
                acc += s_h[4 * r4 + 0] * wv.x + s_h[4 * r4 + 1] * wv.y
                     + s_h[4 * r4 + 2] * wv.z + s_h[4 * r4 + 3] * wv.w;
            }
            lg[k] = acc;
        }
        float m = lg[0];
        #pragma unroll
        for (int k = 1; k < NK; k++) m = fmaxf(m, lg[k]);
        float ssum = 0.0f;
        #pragma unroll
        for (int k = 0; k < NK; k++) { lg[k] = expf(lg[k] - m); ssum += lg[k]; }
        const float inv = 1.0f / ssum;
        #pragma unroll
        for (int k = 0; k < NK; k++)
            g_atten[k * (BATCH * BC) + b * BC + t] = lg[k] * inv;

        __threadfence();
        __syncthreads();
        if (t == 0) atomicExch(&g_ready[b], 1);
    }
    __syncthreads();
}

// ---------------------------------------------------------------------------
__global__ __launch_bounds__(256, 8) void fused_kernel(
    const float* __restrict__ x0, const float* __restrict__ x1,
    const float* __restrict__ W_joint, const float* __restrict__ b_joint,
    const float* __restrict__ bn_gamma, const float* __restrict__ bn_beta,
    const float* __restrict__ bn_mean, const float* __restrict__ bn_var,
    const float* __restrict__ W_group, const float* __restrict__ b_group,
    float* __restrict__ out)
{
    const int t = threadIdx.x;

    __shared__ __align__(16) float s_gap[BC];
    __shared__ __align__(16) float s_h[RC];
    __shared__ __align__(16) float s_red[8];
    __shared__ int s_task;
    __shared__ int s_last;
    __shared__ int s_act;
    __shared__ int s_rtask;

    for (;;) {
        __syncthreads();
        // ------------- dispatch: prefer ready scale work, else reduce -------------
        if (t == 0) {
            int task;
            const int sh = atomicAdd(&g_scale_ticket, 0);     // peek head
            if (sh < NSCHUNK && atomicAdd(&g_ready[sh / CHUNKS_PB], 0) != 0) {
                const int s = atomicAdd(&g_scale_ticket, 1);
                task = (s < NSCHUNK) ? (NRED + s) : -2;
            } else {
                const int r = atomicAdd(&g_red_ticket, 1);
                if (r < NRED) task = r;
                else {
                    const int s = atomicAdd(&g_scale_ticket, 1);
                    task = (s < NSCHUNK) ? (NRED + s) : -2;
                }
            }
            s_task = task;
        }
        __syncthreads();
        const int task = s_task;
        if (task == -2) break;

        if (task < NRED) {
            do_reduce_task(task, t, x0, x1, W_joint, b_joint, bn_gamma, bn_beta,
                           bn_mean, bn_var, W_group, b_group,
                           s_gap, s_h, s_red, &s_last);
            continue;
        }

        // ---------------- scale ticket: batch b, rows [r0, r0+4) ----------------
        const int s  = task - NRED;
        const int b  = s / CHUNKS_PB;
        const int r0 = (s % CHUNKS_PB) * CH_ROWS;

        // If batch b not ready yet: consume reduce tickets instead of spinning.
        for (;;) {
            __syncthreads();
            if (t == 0) {
                if (atomicAdd(&g_ready[b], 0) != 0) s_act = 1;
                else {
                    const int r = atomicAdd(&g_red_ticket, 1);
                    if (r < NRED) { s_act = 2; s_rtask = r; }
                    else          { s_act = 0; __nanosleep(256); }
                }
            }
            __syncthreads();
            if (s_act == 1) break;
            if (s_act == 2)
                do_reduce_task(s_rtask, t, x0, x1, W_joint, b_joint, bn_gamma,
                               bn_beta, bn_mean, bn_var, W_group, b_group,
                               s_gap, s_h, s_red, &s_last);
        }
        __threadfence();

        #pragma unroll
        for (int j = 0; j < CH_ROWS; j++) {
            const int rr = r0 + j;
            const float4* src;
            float4* dst;
            float scale;

            if (rr < C0) {
                const int nb = rr >> 8;
                const int c  = rr & (BC - 1);
                scale = __ldcg(&g_atten[nb * (BATCH * BC) + b * BC + c]);
                const size_t row = (size_t)b * C0 + rr;
                src = (const float4*)(x0 + row * LEN);
                dst = (float4*)(out + row * LEN);
            } else {
                const int r1 = rr - C0;
                const int nb = r1 >> 8;
                const int c  = r1 & (BC - 1);
                scale = __ldcg(&g_atten[(NB0 + nb) * (BATCH * BC) + b * BC + c]);
                const size_t row = (size_t)b * C1 + r1;
                src = (const float4*)(x1 + row * LEN);
                dst = (float4*)(out + (size_t)(BATCH * C0) * LEN + row * LEN);
            }

            float4 v0 = src[t];
            float4 v1 = src[t + 256];
            v0.x *= scale; v0.y *= scale; v0.z *= scale; v0.w *= scale;
            v1.x *= scale; v1.y *= scale; v1.z *= scale; v1.w *= scale;
            __stcs(dst + t,       v0);
            __stcs(dst + t + 256, v1);
        }
    }
}

// ---------------------------------------------------------------------------
extern "C" void kernel_launch(void* const* d_in, const int* in_sizes, int n_in,
                              void* d_out, int out_size) {
    const float* x0       = (const float*)d_in[0];
    const float* x1       = (const float*)d_in[1];
    const float* W_joint  = (const float*)d_in[2];
    const float* b_joint  = (const float*)d_in[3];
    const float* bn_gamma = (const float*)d_in[4];
    const float* bn_beta  = (const float*)d_in[5];
    const float* bn_mean  = (const float*)d_in[6];
    const float* bn_var   = (const float*)d_in[7];
    const float* W_group  = (const float*)d_in[8];
    const float* b_group  = (const float*)d_in[9];
    float* out = (float*)d_out;

    zero_flags_kernel<<<1, 32>>>();
    fused_kernel<<<GRID, 256>>>(x0, x1, W_joint, b_joint, bn_gamma, bn_beta,
                                bn_mean, bn_var, W_group, b_group, out);
}

// round 10
// speedup vs baseline: 5.0630x; 1.3000x over previous
#include <cuda_runtime.h>
#include <cstddef>

#define BATCH 16
#define C0    1024
#define C1    512
#define LEN   2048
#define BC    256
#define RC    64
#define NB0   4
#define NB1   2
#define NK    (NB0 + NB1)
#define EPSV  1e-5f
#define NROWS   (BATCH * (C0 + C1))   // 24576
#define RPB     4                      // rows per scale block
#define NSBLK   (NROWS / RPB)          // 6144

// scratch (allocation-free rule: __device__ globals)
__device__ float g_gap[BATCH * BC];
__device__ float g_atten[NK * BATCH * BC];

// ---------------------------------------------------------------------------
// Kernel 1: gap[b][c] = mean over L of block-sums. One block per (b, c).
// 6 rows x 2048 f32, float4 loads, 12 loads in flight per thread.
// ---------------------------------------------------------------------------
__global__ __launch_bounds__(256) void gap_kernel(const float* __restrict__ x0,
                                                  const float* __restrict__ x1) {
    const int b = blockIdx.x >> 8;
    const int c = blockIdx.x & (BC - 1);
    const int t = threadIdx.x;

    float sum = 0.0f;

    #pragma unroll
    for (int nb = 0; nb < NB0; nb++) {
        const float4* p = (const float4*)(x0 + (size_t)(b * C0 + nb * BC + c) * LEN);
        float4 v0 = p[t];
        float4 v1 = p[t + 256];
        sum += v0.x + v0.y + v0.z + v0.w;
        sum += v1.x + v1.y + v1.z + v1.w;
    }
    #pragma unroll
    for (int nb = 0; nb < NB1; nb++) {
        const float4* p = (const float4*)(x1 + (size_t)(b * C1 + nb * BC + c) * LEN);
        float4 v0 = p[t];
        float4 v1 = p[t + 256];
        sum += v0.x + v0.y + v0.z + v0.w;
        sum += v1.x + v1.y + v1.z + v1.w;
    }

    __shared__ float red[8];
    #pragma unroll
    for (int o = 16; o; o >>= 1) sum += __shfl_down_sync(0xffffffffu, sum, o);
    if ((t & 31) == 0) red[t >> 5] = sum;
    __syncthreads();
    if (t < 8) {
        float s = red[t];
        #pragma unroll
        for (int o = 4; o; o >>= 1) s += __shfl_down_sync(0xffu, s, o);
        if (t == 0) g_gap[b * BC + c] = s * (1.0f / (float)LEN);
    }
}

// ---------------------------------------------------------------------------
// Kernel 2: tiny MLP + grouped linear + softmax over blocks.
// ---------------------------------------------------------------------------
__global__ __launch_bounds__(256) void atten_kernel(
    const float* __restrict__ W_joint,   // [RC, BC]
    const float* __restrict__ b_joint,   // [RC]
    const float* __restrict__ bn_gamma,  // [RC]
    const float* __restrict__ bn_beta,   // [RC]
    const float* __restrict__ bn_mean,   // [RC]
    const float* __restrict__ bn_var,    // [RC]
    const float* __restrict__ W_group,   // [NK, BC, RC]
    const float* __restrict__ b_group)   // [NK, BC]
{
    const int b = blockIdx.x;
    const int t = threadIdx.x;

    __shared__ __align__(16) float s_gap[BC];
    __shared__ __align__(16) float s_h[RC];

    s_gap[t] = g_gap[b * BC + t];
    __syncthreads();

    if (t < RC) {
        float acc = b_joint[t];
        const float4* w = (const float4*)(W_joint + t * BC);
        const float4* g4 = (const float4*)s_gap;
        #pragma unroll 8
        for (int c4 = 0; c4 < BC / 4; c4++) {
            float4 wv = w[c4];
            float4 gv = g4[c4];
            acc += wv.x * gv.x + wv.y * gv.y + wv.z * gv.z + wv.w * gv.w;
        }
        acc = (acc - bn_mean[t]) * rsqrtf(bn_var[t] + EPSV) * bn_gamma[t] + bn_beta[t];
        s_h[t] = fmaxf(acc, 0.0f);
    }
    __syncthreads();

    float lg[NK];
    #pragma unroll
    for (int k = 0; k < NK; k++) {
        float acc = b_group[k * BC + t];
        const float4* w = (const float4*)(W_group + (size_t)(k * BC + t) * RC);
        #pragma unroll
        for (int r4 = 0; r4 < RC / 4; r4++) {
            float4 wv = w[r4];
            acc += s_h[4 * r4 + 0] * wv.x + s_h[4 * r4 + 1] * wv.y
                 + s_h[4 * r4 + 2] * wv.z + s_h[4 * r4 + 3] * wv.w;
        }
        lg[k] = acc;
    }
    float m = lg[0];
    #pragma unroll
    for (int k = 1; k < NK; k++) m = fmaxf(m, lg[k]);
    float ssum = 0.0f;
    #pragma unroll
    for (int k = 0; k < NK; k++) { lg[k] = expf(lg[k] - m); ssum += lg[k]; }
    const float inv = 1.0f / ssum;
    #pragma unroll
    for (int k = 0; k < NK; k++)
        g_atten[k * (BATCH * BC) + b * BC + t] = lg[k] * inv;
}

// ---------------------------------------------------------------------------
// Kernel 3: out = x * atten. FOUR rows per block (reversed scan).
// Per thread: 8 independent float4 loads issued as a front batch (MLP=8),
// then 8 streaming stores as a write burst. 6144 blocks.
// ---------------------------------------------------------------------------
__global__ __launch_bounds__(256) void scale_kernel(const float* __restrict__ x0,
                                                    const float* __restrict__ x1,
                                                    float* __restrict__ out) {
    const int g  = (NSBLK - 1) - blockIdx.x;   // reversed scan
    const int t  = threadIdx.x;
    const int r0 = g * RPB;                    // first global row of this block

    const float4* src[RPB];
    float4*       dst[RPB];
    float         scl[RPB];

    #pragma unroll
    for (int j = 0; j < RPB; j++) {
        const int row = r0 + j;
        if (row < BATCH * C0) {
            const int b  = row >> 10;
            const int ch = row & (C0 - 1);
            const int nb = ch >> 8;
            const int c  = ch & (BC - 1);
            scl[j] = __ldg(&g_atten[nb * (BATCH * BC) + b * BC + c]);
            src[j] = (const float4*)(x0 + (size_t)row * LEN);
            dst[j] = (float4*)(out + (size_t)row * LEN);
        } else {
            const int r  = row - BATCH * C0;
            const int b  = r >> 9;
            const int ch = r & (C1 - 1);
            const int nb = ch >> 8;
            const int c  = ch & (BC - 1);
            scl[j] = __ldg(&g_atten[(NB0 + nb) * (BATCH * BC) + b * BC + c]);
            src[j] = (const float4*)(x1 + (size_t)r * LEN);
            dst[j] = (float4*)(out + (size_t)(BATCH * C0) * LEN + (size_t)r * LEN);
        }
    }

    // front-batched reads: 8 independent LDG.128
    float4 v[RPB][2];
    #pragma unroll
    for (int j = 0; j < RPB; j++) {
        v[j][0] = src[j][t];
        v[j][1] = src[j][t + 256];
    }

    // scale + write burst
    #pragma unroll
    for (int j = 0; j < RPB; j++) {
        const float s = scl[j];
        #pragma unroll
        for (int i = 0; i < 2; i++) {
            float4 o = v[j][i];
            o.x *= s; o.y *= s; o.z *= s; o.w *= s;
            __stcs(dst[j] + t + i * 256, o);
        }
    }
}

// ---------------------------------------------------------------------------
extern "C" void kernel_launch(void* const* d_in, const int* in_sizes, int n_in,
                              void* d_out, int out_size) {
    const float* x0       = (const float*)d_in[0];
    const float* x1       = (const float*)d_in[1];
    const float* W_joint  = (const float*)d_in[2];
    const float* b_joint  = (const float*)d_in[3];
    const float* bn_gamma = (const float*)d_in[4];
    const float* bn_beta  = (const float*)d_in[5];
    const float* bn_mean  = (const float*)d_in[6];
    const float* bn_var   = (const float*)d_in[7];
    const float* W_group  = (const float*)d_in[8];
    const float* b_group  = (const float*)d_in[9];
    float* out = (float*)d_out;

    gap_kernel<<<BATCH * BC, 256>>>(x0, x1);
    atten_kernel<<<BATCH, 256>>>(W_joint, b_joint, bn_gamma, bn_beta,
                                 bn_mean, bn_var, W_group, b_group);
    scale_kernel<<<NSBLK, 256>>>(x0, x1, out);
}